// round 6
// baseline (speedup 1.0000x reference)
#include <cuda_runtime.h>
#include <cuda_bf16.h>
#include <stdint.h>
#include <math.h>

#define B 16
#define S 8192
#define D 512
#define H 1024

#define MT 128      // CTA M tile
#define NTT 128     // CTA N tile
#define KC 64       // K chunk (floats)
#define NCH 8       // 512/64

// Padded smem row: 68 floats (272 B) -> conflict-free fragment LDS
#define ROWB 272u
#define AST 0u
#define BST 34816u          // 128 * 272
#define STG2 69632u         // A + B stage
#define SMEM_BYTES (2u * STG2 + 4096u)

// ---------------------------------------------------------------------------
// Static scratch (no allocations allowed)
// ---------------------------------------------------------------------------
__device__ float g_hb[B * H];
__device__ float g_w[B * S];
__device__ float g_spart[8][B * S];
__device__ float g_part[B * 64 * D];
__device__ uint32_t g_w1t[H * D];   // W1 rounded to tf32 (bit pattern)

// ---------------------------------------------------------------------------
// Helpers
// ---------------------------------------------------------------------------
__device__ __forceinline__ uint32_t smem_u32(const void* p) {
    uint32_t a;
    asm("{ .reg .u64 t; cvta.to.shared.u64 t, %1; cvt.u32.u64 %0, t; }" : "=r"(a) : "l"(p));
    return a;
}
__device__ __forceinline__ void cp16(uint32_t dst, const void* src) {
    asm volatile("cp.async.cg.shared.global [%0], [%1], 16;" :: "r"(dst), "l"(src));
}
__device__ __forceinline__ uint32_t cvt_tf32(float x) {
    uint32_t r;
    asm("cvt.rna.tf32.f32 %0, %1;" : "=r"(r) : "f"(x));
    return r;
}
__device__ __forceinline__ uint32_t lds32(uint32_t addr) {
    uint32_t r;
    asm volatile("ld.shared.b32 %0, [%1];" : "=r"(r) : "r"(addr));
    return r;
}
__device__ __forceinline__ void mma_tf32(float* d, const uint32_t* a, const uint32_t* b) {
    asm volatile(
        "mma.sync.aligned.m16n8k8.row.col.f32.tf32.tf32.f32 "
        "{%0,%1,%2,%3}, {%4,%5,%6,%7}, {%8,%9}, {%0,%1,%2,%3};"
        : "+f"(d[0]), "+f"(d[1]), "+f"(d[2]), "+f"(d[3])
        : "r"(a[0]), "r"(a[1]), "r"(a[2]), "r"(a[3]), "r"(b[0]), "r"(b[1]));
}
__device__ __forceinline__ float tanh_fast(float x) {
    float e = __expf(2.0f * x);
    return 1.0f - __fdividef(2.0f, e + 1.0f);  // = tanh(x), no NaN at +/-inf
}

// ---------------------------------------------------------------------------
// W1 prepass: round W[:, :512] to tf32
// ---------------------------------------------------------------------------
__global__ void w1cvt_kernel(const float* __restrict__ W) {
    int o = blockIdx.x;
    for (int k = threadIdx.x; k < D; k += 256)
        g_w1t[o * D + k] = cvt_tf32(W[(size_t)o * H + k]);
}

// ---------------------------------------------------------------------------
// g_hb[b][o] = bias[o] + hidden[b] @ W[:, 512:]   (exact fp32)
// ---------------------------------------------------------------------------
__global__ void hb_kernel(const float* __restrict__ hidden,
                          const float* __restrict__ W,
                          const float* __restrict__ bias) {
    __shared__ float hs[D];
    int b = blockIdx.x;
    for (int i = threadIdx.x; i < D; i += 256) hs[i] = hidden[b * D + i];
    __syncthreads();
    for (int j = 0; j < 4; j++) {
        int o = threadIdx.x + j * 256;
        const float4* wr = (const float4*)(W + (size_t)o * H + D);
        float acc = 0.f;
#pragma unroll 8
        for (int d4 = 0; d4 < D / 4; d4++) {
            float4 w4 = wr[d4];
            acc += hs[d4 * 4 + 0] * w4.x + hs[d4 * 4 + 1] * w4.y +
                   hs[d4 * 4 + 2] * w4.z + hs[d4 * 4 + 3] * w4.w;
        }
        g_hb[b * H + o] = acc + bias[o];
    }
}

// ---------------------------------------------------------------------------
// Dominant kernel: single-pass TF32 GEMM via mma.m16n8k8 + fused tanh-dot-v.
// Grid (8 N-tiles, 1024 M-tiles), 256 threads, warp tile 64x32.
// ---------------------------------------------------------------------------
__device__ __forceinline__ void stsA_tf32(uint32_t aBase, const float4* pA,
                                          int ar0, int f4) {
#pragma unroll
    for (int p = 0; p < 8; p++) {
        float4 x = pA[p];
        uint32_t t0 = cvt_tf32(x.x), t1 = cvt_tf32(x.y);
        uint32_t t2 = cvt_tf32(x.z), t3 = cvt_tf32(x.w);
        uint32_t addr = aBase + (uint32_t)(ar0 + 16 * p) * ROWB + (uint32_t)f4 * 16u;
        asm volatile("st.shared.v4.b32 [%0], {%1,%2,%3,%4};"
                     :: "r"(addr), "r"(t0), "r"(t1), "r"(t2), "r"(t3));
    }
}

__global__ void __launch_bounds__(256, 1)
scores_kernel(const float* __restrict__ enc, const float* __restrict__ v) {
    extern __shared__ char smem[];
    uint32_t sb = smem_u32(smem);
    const int tid = threadIdx.x;
    const int lane = tid & 31, wid = tid >> 5;
    const int nt = blockIdx.x;   // 0..7
    const int mt = blockIdx.y;   // 0..1023
    const int base = mt * MT;
    const int b = base >> 13;    // S=8192
    const int wM = wid >> 2, wN = wid & 3;
    const int gn0 = nt * NTT;

    float* hb_s = (float*)(smem + 2 * STG2);
    float* v_s = (float*)(smem + 2 * STG2 + 512);
    float* sred = (float*)(smem + 2 * STG2 + 1024);

    if (tid < NTT) {
        hb_s[tid] = g_hb[b * H + gn0 + tid];
        v_s[tid] = v[gn0 + tid];
    }

    // A loader: 16 threads/row-group, 8 rows each
    const int f4 = tid & 15;
    const int ar0 = tid >> 4;
    // B loader: one row per thread (tid&127), 8 x 16B chunks
    const int brow = tid & 127;
    const int bhalf = tid >> 7;

    float acc[4][4][4];
#pragma unroll
    for (int i = 0; i < 4; i++)
#pragma unroll
        for (int j = 0; j < 4; j++)
#pragma unroll
            for (int q = 0; q < 4; q++) acc[i][j][q] = 0.f;

    float4 pA[8];
    // ---- prologue: chunk 0 ----
#pragma unroll
    for (int p = 0; p < 8; p++)
        pA[p] = *(const float4*)(enc + (size_t)(base + ar0 + 16 * p) * D + f4 * 4);
    stsA_tf32(sb + AST, pA, ar0, f4);
    {
        const char* src = (const char*)g_w1t + ((size_t)(gn0 + brow) * D) * 4 + bhalf * 128;
#pragma unroll
        for (int c = 0; c < 8; c++)
            cp16(sb + BST + brow * ROWB + bhalf * 128u + c * 16u, src + c * 16);
        asm volatile("cp.async.commit_group;" ::: "memory");
    }
#pragma unroll
    for (int p = 0; p < 8; p++)
        pA[p] = *(const float4*)(enc + (size_t)(base + ar0 + 16 * p) * D + KC + f4 * 4);

    // fragment base offsets (bytes within stage)
    const uint32_t aoff = (uint32_t)(wM * 64 + (lane >> 2)) * ROWB + (uint32_t)(lane & 3) * 4u;
    const uint32_t boff = BST + (uint32_t)(wN * 32 + (lane >> 2)) * ROWB + (uint32_t)(lane & 3) * 4u;

    for (int i = 0; i < NCH; i++) {
        const int s = i & 1;
        const uint32_t stg = sb + s * STG2;
        const uint32_t stgN = sb + (1 - s) * STG2;
        if (i + 1 < NCH) {
            stsA_tf32(stgN + AST, pA, ar0, f4);
            const int kb = (i + 1) * KC;
            const char* src = (const char*)g_w1t + ((size_t)(gn0 + brow) * D + kb) * 4 + bhalf * 128;
#pragma unroll
            for (int c = 0; c < 8; c++)
                cp16(stgN + BST + brow * ROWB + bhalf * 128u + c * 16u, src + c * 16);
            asm volatile("cp.async.commit_group;" ::: "memory");
        }
        if (i + 2 < NCH) {
#pragma unroll
            for (int p = 0; p < 8; p++)
                pA[p] = *(const float4*)(enc + (size_t)(base + ar0 + 16 * p) * D +
                                         (i + 2) * KC + f4 * 4);
        }
        if (i + 1 < NCH) asm volatile("cp.async.wait_group 1;" ::: "memory");
        else             asm volatile("cp.async.wait_group 0;" ::: "memory");
        __syncthreads();

        // ---- compute chunk i: 8 k8-steps ----
#pragma unroll
        for (int kk = 0; kk < 8; kk++) {
            const uint32_t kbyte = (uint32_t)kk * 32u;
            uint32_t a[4][4], bfr[4][2];
#pragma unroll
            for (int t = 0; t < 4; t++) {
                uint32_t ad = stg + aoff + (uint32_t)t * (16u * ROWB) + kbyte;
                a[t][0] = lds32(ad);
                a[t][1] = lds32(ad + 8u * ROWB);
                a[t][2] = lds32(ad + 16u);
                a[t][3] = lds32(ad + 8u * ROWB + 16u);
            }
#pragma unroll
            for (int j = 0; j < 4; j++) {
                uint32_t bd = stg + boff + (uint32_t)j * (8u * ROWB) + kbyte;
                bfr[j][0] = lds32(bd);
                bfr[j][1] = lds32(bd + 16u);
            }
#pragma unroll
            for (int t = 0; t < 4; t++)
#pragma unroll
                for (int j = 0; j < 4; j++)
                    mma_tf32(acc[t][j], a[t], bfr[j]);
        }
        __syncthreads();
    }

    // ---- epilogue: tanh + v-dot, deterministic reduction ----
    const int cq = (lane & 3) * 2;
    const int rr = lane >> 2;
#pragma unroll
    for (int t = 0; t < 4; t++) {
        float slo = 0.f, shi = 0.f;
#pragma unroll
        for (int j = 0; j < 4; j++) {
            int c = wN * 32 + j * 8 + cq;
            float v0 = v_s[c], v1 = v_s[c + 1];
            float h0 = hb_s[c], h1 = hb_s[c + 1];
            slo += v0 * tanh_fast(acc[t][j][0] + h0) + v1 * tanh_fast(acc[t][j][1] + h1);
            shi += v0 * tanh_fast(acc[t][j][2] + h0) + v1 * tanh_fast(acc[t][j][3] + h1);
        }
        slo += __shfl_xor_sync(0xffffffffu, slo, 1);
        slo += __shfl_xor_sync(0xffffffffu, slo, 2);
        shi += __shfl_xor_sync(0xffffffffu, shi, 1);
        shi += __shfl_xor_sync(0xffffffffu, shi, 2);
        if ((lane & 3) == 0) {
            sred[(wM * 64 + t * 16 + rr) * 5 + wN] = slo;
            sred[(wM * 64 + t * 16 + rr + 8) * 5 + wN] = shi;
        }
    }
    __syncthreads();
    if (tid < MT) {
        float ssum = sred[tid * 5 + 0] + sred[tid * 5 + 1] +
                     sred[tid * 5 + 2] + sred[tid * 5 + 3];
        g_spart[nt][(size_t)base + tid] = ssum;
    }
}

// ---------------------------------------------------------------------------
// Softmax over S per batch (sums the 8 N-tile partials; deterministic)
// ---------------------------------------------------------------------------
__global__ void softmax_kernel() {
    __shared__ float red[32];
    int b = blockIdx.x, tid = threadIdx.x;  // 1024 threads
    float vals[8];
    float vmax = -1e30f;
#pragma unroll
    for (int i = 0; i < 8; i++) {
        size_t idx = (size_t)b * S + tid + i * 1024;
        float a = 0.f;
#pragma unroll
        for (int t = 0; t < 8; t++) a += g_spart[t][idx];
        vals[i] = a;
        vmax = fmaxf(vmax, a);
    }
#pragma unroll
    for (int off = 16; off; off >>= 1)
        vmax = fmaxf(vmax, __shfl_xor_sync(0xffffffffu, vmax, off));
    if ((tid & 31) == 0) red[tid >> 5] = vmax;
    __syncthreads();
    if (tid < 32) {
        float m = red[tid];
#pragma unroll
        for (int off = 16; off; off >>= 1)
            m = fmaxf(m, __shfl_xor_sync(0xffffffffu, m, off));
        red[tid] = m;
    }
    __syncthreads();
    vmax = red[0];
    __syncthreads();
    float sum = 0.f;
#pragma unroll
    for (int i = 0; i < 8; i++) {
        vals[i] = expf(vals[i] - vmax);
        sum += vals[i];
    }
#pragma unroll
    for (int off = 16; off; off >>= 1) sum += __shfl_xor_sync(0xffffffffu, sum, off);
    if ((tid & 31) == 0) red[tid >> 5] = sum;
    __syncthreads();
    if (tid < 32) {
        float s2 = red[tid];
#pragma unroll
        for (int off = 16; off; off >>= 1) s2 += __shfl_xor_sync(0xffffffffu, s2, off);
        red[tid] = s2;
    }
    __syncthreads();
    float inv = 1.0f / red[0];
#pragma unroll
    for (int i = 0; i < 8; i++)
        g_w[(size_t)b * S + tid + i * 1024] = vals[i] * inv;
}

// ---------------------------------------------------------------------------
// Context: two-stage deterministic reduction
// ---------------------------------------------------------------------------
__global__ void ctx_part_kernel(const float* __restrict__ enc) {
    int chunk = blockIdx.x;  // 64
    int b = blockIdx.y;      // 16
    int tid = threadIdx.x;   // 128
    const float* wp = g_w + (size_t)b * S + chunk * 128;
    const float4* ep = (const float4*)(enc + ((size_t)b * S + chunk * 128) * D) + tid;
    float4 a0 = make_float4(0.f, 0.f, 0.f, 0.f);
    float4 a1 = make_float4(0.f, 0.f, 0.f, 0.f);
#pragma unroll 4
    for (int s = 0; s < 128; s += 2) {
        float w0 = wp[s], w1 = wp[s + 1];
        float4 e0 = ep[(size_t)s * (D / 4)];
        float4 e1 = ep[(size_t)(s + 1) * (D / 4)];
        a0.x += w0 * e0.x; a0.y += w0 * e0.y; a0.z += w0 * e0.z; a0.w += w0 * e0.w;
        a1.x += w1 * e1.x; a1.y += w1 * e1.y; a1.z += w1 * e1.z; a1.w += w1 * e1.w;
    }
    a0.x += a1.x; a0.y += a1.y; a0.z += a1.z; a0.w += a1.w;
    *(float4*)&g_part[((size_t)b * 64 + chunk) * D + tid * 4] = a0;
}

__global__ void ctx_reduce_kernel(float* __restrict__ out) {
    int b = blockIdx.x;
    int d = threadIdx.x;
    float acc = 0.f;
#pragma unroll
    for (int c = 0; c < 64; c++) acc += g_part[((size_t)b * 64 + c) * D + d];
    out[b * D + d] = acc;
}

// ---------------------------------------------------------------------------
extern "C" void kernel_launch(void* const* d_in, const int* in_sizes, int n_in,
                              void* d_out, int out_size) {
    const float* enc = (const float*)d_in[0];
    const float* hidden = (const float*)d_in[1];
    const float* W = (const float*)d_in[2];
    const float* bias = (const float*)d_in[3];
    const float* v = (const float*)d_in[4];
    float* out = (float*)d_out;

    cudaFuncSetAttribute(scores_kernel, cudaFuncAttributeMaxDynamicSharedMemorySize,
                         SMEM_BYTES);

    w1cvt_kernel<<<H, 256>>>(W);
    hb_kernel<<<B, 256>>>(hidden, W, bias);
    dim3 grid(8, (B * S) / MT);
    scores_kernel<<<grid, 256, SMEM_BYTES>>>(enc, v);
    softmax_kernel<<<B, 1024>>>();
    dim3 g4(64, B);
    ctx_part_kernel<<<g4, 128>>>(enc);
    ctx_reduce_kernel<<<B, D>>>(out);
}

// round 7
// speedup vs baseline: 1.1029x; 1.1029x over previous
#include <cuda_runtime.h>
#include <cuda_bf16.h>
#include <stdint.h>
#include <math.h>

#define B 16
#define S 8192
#define D 512
#define H 1024

#define MT 128      // CTA M tile
#define NTT 128     // CTA N tile
#define KC 64       // K chunk (bf16, 128B rows = SW128)
#define NCH 8       // 512/64
#define NTH 512     // 16 warps

// ---------------------------------------------------------------------------
// Static scratch (no allocations allowed)
// ---------------------------------------------------------------------------
__device__ float g_hb[B * H];
__device__ float g_w[B * S];
__device__ float g_spart[8][B * S];
__device__ float g_part[B * 64 * D];
__device__ __nv_bfloat16 g_w1hi[H * D];
__device__ __nv_bfloat16 g_w1lo[H * D];

// ---------------------------------------------------------------------------
// Helpers
// ---------------------------------------------------------------------------
__device__ __forceinline__ uint32_t smem_u32(const void* p) {
    uint32_t a;
    asm("{ .reg .u64 t; cvta.to.shared.u64 t, %1; cvt.u32.u64 %0, t; }" : "=r"(a) : "l"(p));
    return a;
}
#define SWZ(off) ((off) ^ (((off) >> 3) & 0x70))

__device__ __forceinline__ void cp16(uint32_t dst, const void* src) {
    asm volatile("cp.async.cg.shared.global [%0], [%1], 16;" :: "r"(dst), "l"(src));
}
__device__ __forceinline__ void ldm4(uint32_t* r, uint32_t addr) {
    asm volatile("ldmatrix.sync.aligned.m8n8.x4.shared.b16 {%0,%1,%2,%3}, [%4];"
                 : "=r"(r[0]), "=r"(r[1]), "=r"(r[2]), "=r"(r[3]) : "r"(addr));
}
__device__ __forceinline__ void mma16816(float* d, const uint32_t* a, const uint32_t* b) {
    asm volatile(
        "mma.sync.aligned.m16n8k16.row.col.f32.bf16.bf16.f32 "
        "{%0,%1,%2,%3}, {%4,%5,%6,%7}, {%8,%9}, {%0,%1,%2,%3};"
        : "+f"(d[0]), "+f"(d[1]), "+f"(d[2]), "+f"(d[3])
        : "r"(a[0]), "r"(a[1]), "r"(a[2]), "r"(a[3]), "r"(b[0]), "r"(b[1]));
}
__device__ __forceinline__ float tanh_fast(float x) {
    float e = __expf(2.0f * x);
    return 1.0f - __fdividef(2.0f, e + 1.0f);  // = tanh(x), no NaN at +/-inf
}

// ---------------------------------------------------------------------------
// W1 split prepass: W[:, :512] -> bf16 hi/lo (K-major rows of length 512)
// ---------------------------------------------------------------------------
__global__ void w1cvt_kernel(const float* __restrict__ W) {
    int o = blockIdx.x;
    for (int k = threadIdx.x; k < D; k += 256) {
        float x = W[(size_t)o * H + k];
        __nv_bfloat16 h = __float2bfloat16(x);
        g_w1hi[o * D + k] = h;
        g_w1lo[o * D + k] = __float2bfloat16(x - __bfloat162float(h));
    }
}

// ---------------------------------------------------------------------------
// g_hb[b][o] = bias[o] + hidden[b] @ W[:, 512:]
// ---------------------------------------------------------------------------
__global__ void hb_kernel(const float* __restrict__ hidden,
                          const float* __restrict__ W,
                          const float* __restrict__ bias) {
    __shared__ float hs[D];
    int b = blockIdx.x;
    for (int i = threadIdx.x; i < D; i += 256) hs[i] = hidden[b * D + i];
    __syncthreads();
    for (int j = 0; j < 4; j++) {
        int o = threadIdx.x + j * 256;
        const float4* wr = (const float4*)(W + (size_t)o * H + D);
        float acc = 0.f;
#pragma unroll 8
        for (int d4 = 0; d4 < D / 4; d4++) {
            float4 w4 = wr[d4];
            acc += hs[d4 * 4 + 0] * w4.x + hs[d4 * 4 + 1] * w4.y +
                   hs[d4 * 4 + 2] * w4.z + hs[d4 * 4 + 3] * w4.w;
        }
        g_hb[b * H + o] = acc + bias[o];
    }
}

// ---------------------------------------------------------------------------
// Dominant kernel: 3xBF16-split GEMM via mma.sync + fused tanh-dot-v.
// Grid (8 N-tiles, 1024 M-tiles), 512 threads, 16 warps, warp tile 32x32.
// smem: 2 stages x 64KB { Ahi 16K | Alo 16K | Bhi 16K | Blo 16K } + extras
// ---------------------------------------------------------------------------
#define STG 65536u
#define SMEM_BYTES (2u * STG + 4096u)

__device__ __forceinline__ void stsA(uint32_t aBase, const float4* pA, int ar0, int f4) {
#pragma unroll
    for (int p = 0; p < 4; p++) {
        float4 x = pA[p];
        uint32_t h0, h1, l0, l1;
        asm("cvt.rn.satfinite.bf16x2.f32 %0, %1, %2;" : "=r"(h0) : "f"(x.y), "f"(x.x));
        asm("cvt.rn.satfinite.bf16x2.f32 %0, %1, %2;" : "=r"(h1) : "f"(x.w), "f"(x.z));
        float lx = x.x - __uint_as_float(h0 << 16);
        float ly = x.y - __uint_as_float(h0 & 0xFFFF0000u);
        float lz = x.z - __uint_as_float(h1 << 16);
        float lw = x.w - __uint_as_float(h1 & 0xFFFF0000u);
        asm("cvt.rn.satfinite.bf16x2.f32 %0, %1, %2;" : "=r"(l0) : "f"(ly), "f"(lx));
        asm("cvt.rn.satfinite.bf16x2.f32 %0, %1, %2;" : "=r"(l1) : "f"(lw), "f"(lz));
        uint32_t sw = SWZ((uint32_t)((ar0 + 32 * p) * 128 + f4 * 8));
        asm volatile("st.shared.v2.b32 [%0], {%1,%2};" :: "r"(aBase + sw), "r"(h0), "r"(h1));
        asm volatile("st.shared.v2.b32 [%0], {%1,%2};" :: "r"(aBase + 16384u + sw), "r"(l0), "r"(l1));
    }
}

__global__ void __launch_bounds__(NTH, 1)
scores_kernel(const float* __restrict__ enc, const float* __restrict__ v) {
    extern __shared__ char smem[];
    uint32_t sb = smem_u32(smem);
    const int tid = threadIdx.x;
    const int lane = tid & 31, wid = tid >> 5;
    const int nt = blockIdx.x;   // 0..7
    const int mt = blockIdx.y;   // 0..1023
    const int base = mt * MT;
    const int b = base >> 13;    // S=8192
    const int wM = wid >> 2, wN = wid & 3;   // 4x4 warp grid, tile 32x32
    const int gn0 = nt * NTT;

    float* hb_s = (float*)(smem + 2 * STG);
    float* v_s = (float*)(smem + 2 * STG + 512);
    float* sred = (float*)(smem + 2 * STG + 1024);

    if (tid < NTT) {
        hb_s[tid] = g_hb[b * H + gn0 + tid];
        v_s[tid] = v[gn0 + tid];
    }

    // A loader: f4 = float4 slot in row (16/row), rows ar0 + 32p
    const int f4 = tid & 15;
    const int ar0 = tid >> 4;       // 0..31
    // B loader: row brow, two 16B chunks starting at bc0
    const int brow = tid >> 2;      // 0..127
    const int bc0 = (tid & 3) * 2;  // 0,2,4,6

    float acc[2][4][4];
#pragma unroll
    for (int i = 0; i < 2; i++)
#pragma unroll
        for (int j = 0; j < 4; j++)
#pragma unroll
            for (int q = 0; q < 4; q++) acc[i][j][q] = 0.f;

    float4 pA[4];
    // ---- prologue: chunk0 ----
#pragma unroll
    for (int p = 0; p < 4; p++)
        pA[p] = *(const float4*)(enc + (size_t)(base + ar0 + 32 * p) * D + f4 * 4);
    stsA(sb, pA, ar0, f4);
    {
        const char* sH = (const char*)(g_w1hi + (size_t)(gn0 + brow) * D);
        const char* sL = (const char*)(g_w1lo + (size_t)(gn0 + brow) * D);
#pragma unroll
        for (int c = 0; c < 2; c++) {
            uint32_t sw = SWZ((uint32_t)(brow * 128 + (bc0 + c) * 16));
            cp16(sb + 32768u + sw, sH + (bc0 + c) * 16);
            cp16(sb + 49152u + sw, sL + (bc0 + c) * 16);
        }
        asm volatile("cp.async.commit_group;" ::: "memory");
    }
#pragma unroll
    for (int p = 0; p < 4; p++)
        pA[p] = *(const float4*)(enc + (size_t)(base + ar0 + 32 * p) * D + KC + f4 * 4);

    // frag lane addressing (constant per thread)
    const int arow = wM * 32 + (lane & 15);
    const int achk = lane >> 4;                       // 0/1 (16B chunk within kstep)
    const int bro = wN * 32 + ((lane >> 4) & 1) * 8 + (lane & 7);
    const int bchk = (lane >> 3) & 1;

    for (int i = 0; i < NCH; i++) {
        const int s = i & 1;
        const uint32_t stg = sb + s * STG;
        const uint32_t stgN = sb + (1 - s) * STG;
        if (i + 1 < NCH) {
            stsA(stgN, pA, ar0, f4);
            const int kb = (i + 1) * KC;
            const char* sH = (const char*)(g_w1hi + (size_t)(gn0 + brow) * D + kb);
            const char* sL = (const char*)(g_w1lo + (size_t)(gn0 + brow) * D + kb);
#pragma unroll
            for (int c = 0; c < 2; c++) {
                uint32_t sw = SWZ((uint32_t)(brow * 128 + (bc0 + c) * 16));
                cp16(stgN + 32768u + sw, sH + (bc0 + c) * 16);
                cp16(stgN + 49152u + sw, sL + (bc0 + c) * 16);
            }
            asm volatile("cp.async.commit_group;" ::: "memory");
        }
        if (i + 2 < NCH) {
#pragma unroll
            for (int p = 0; p < 4; p++)
                pA[p] = *(const float4*)(enc + (size_t)(base + ar0 + 32 * p) * D +
                                         (i + 2) * KC + f4 * 4);
        }
        if (i + 1 < NCH) asm volatile("cp.async.wait_group 1;" ::: "memory");
        else             asm volatile("cp.async.wait_group 0;" ::: "memory");
        __syncthreads();

        // ---- compute chunk i ----
        const uint32_t aB = stg, bB = stg + 32768u;
#pragma unroll
        for (int kk = 0; kk < 4; kk++) {
            uint32_t ah[2][4], al[2][4], bh[4][2], bl[4][2];
#pragma unroll
            for (int t = 0; t < 2; t++) {
                uint32_t ad = aB + SWZ((uint32_t)((arow + t * 16) * 128 + (kk * 2 + achk) * 16));
                ldm4(ah[t], ad);
                ldm4(al[t], ad + 16384u);
            }
#pragma unroll
            for (int jj = 0; jj < 2; jj++) {
                uint32_t tmp[4];
                uint32_t bd = bB + SWZ((uint32_t)((bro + jj * 16) * 128 + (kk * 2 + bchk) * 16));
                ldm4(tmp, bd);
                bh[2 * jj][0] = tmp[0]; bh[2 * jj][1] = tmp[1];
                bh[2 * jj + 1][0] = tmp[2]; bh[2 * jj + 1][1] = tmp[3];
                ldm4(tmp, bd + 16384u);
                bl[2 * jj][0] = tmp[0]; bl[2 * jj][1] = tmp[1];
                bl[2 * jj + 1][0] = tmp[2]; bl[2 * jj + 1][1] = tmp[3];
            }
#pragma unroll
            for (int t = 0; t < 2; t++)
#pragma unroll
                for (int j = 0; j < 4; j++) {
                    mma16816(acc[t][j], ah[t], bh[j]);
                    mma16816(acc[t][j], ah[t], bl[j]);
                    mma16816(acc[t][j], al[t], bh[j]);
                }
        }
        __syncthreads();
    }

    // ---- epilogue: tanh + v-dot, deterministic reduction ----
    const int cq = (lane & 3) * 2;
    const int rr = lane >> 2;
#pragma unroll
    for (int t = 0; t < 2; t++) {
        float slo = 0.f, shi = 0.f;
#pragma unroll
        for (int j = 0; j < 4; j++) {
            int c = wN * 32 + j * 8 + cq;
            float v0 = v_s[c], v1 = v_s[c + 1];
            float h0 = hb_s[c], h1 = hb_s[c + 1];
            slo += v0 * tanh_fast(acc[t][j][0] + h0) + v1 * tanh_fast(acc[t][j][1] + h1);
            shi += v0 * tanh_fast(acc[t][j][2] + h0) + v1 * tanh_fast(acc[t][j][3] + h1);
        }
        slo += __shfl_xor_sync(0xffffffffu, slo, 1);
        slo += __shfl_xor_sync(0xffffffffu, slo, 2);
        shi += __shfl_xor_sync(0xffffffffu, shi, 1);
        shi += __shfl_xor_sync(0xffffffffu, shi, 2);
        if ((lane & 3) == 0) {
            sred[(wM * 32 + t * 16 + rr) * 5 + wN] = slo;
            sred[(wM * 32 + t * 16 + rr + 8) * 5 + wN] = shi;
        }
    }
    __syncthreads();
    if (tid < MT) {
        float ssum = sred[tid * 5 + 0] + sred[tid * 5 + 1] +
                     sred[tid * 5 + 2] + sred[tid * 5 + 3];
        g_spart[nt][(size_t)base + tid] = ssum;
    }
}

// ---------------------------------------------------------------------------
// Softmax over S per batch (sums the 8 N-tile partials; deterministic)
// ---------------------------------------------------------------------------
__global__ void softmax_kernel() {
    __shared__ float red[32];
    int b = blockIdx.x, tid = threadIdx.x;  // 1024 threads
    float vals[8];
    float vmax = -1e30f;
#pragma unroll
    for (int i = 0; i < 8; i++) {
        size_t idx = (size_t)b * S + tid + i * 1024;
        float a = 0.f;
#pragma unroll
        for (int t = 0; t < 8; t++) a += g_spart[t][idx];
        vals[i] = a;
        vmax = fmaxf(vmax, a);
    }
#pragma unroll
    for (int off = 16; off; off >>= 1)
        vmax = fmaxf(vmax, __shfl_xor_sync(0xffffffffu, vmax, off));
    if ((tid & 31) == 0) red[tid >> 5] = vmax;
    __syncthreads();
    if (tid < 32) {
        float m = red[tid];
#pragma unroll
        for (int off = 16; off; off >>= 1)
            m = fmaxf(m, __shfl_xor_sync(0xffffffffu, m, off));
        red[tid] = m;
    }
    __syncthreads();
    vmax = red[0];
    __syncthreads();
    float sum = 0.f;
#pragma unroll
    for (int i = 0; i < 8; i++) {
        vals[i] = expf(vals[i] - vmax);
        sum += vals[i];
    }
#pragma unroll
    for (int off = 16; off; off >>= 1) sum += __shfl_xor_sync(0xffffffffu, sum, off);
    if ((tid & 31) == 0) red[tid >> 5] = sum;
    __syncthreads();
    if (tid < 32) {
        float s2 = red[tid];
#pragma unroll
        for (int off = 16; off; off >>= 1) s2 += __shfl_xor_sync(0xffffffffu, s2, off);
        red[tid] = s2;
    }
    __syncthreads();
    float inv = 1.0f / red[0];
#pragma unroll
    for (int i = 0; i < 8; i++)
        g_w[(size_t)b * S + tid + i * 1024] = vals[i] * inv;
}

// ---------------------------------------------------------------------------
// Context: two-stage deterministic reduction
// ---------------------------------------------------------------------------
__global__ void ctx_part_kernel(const float* __restrict__ enc) {
    int chunk = blockIdx.x;  // 64
    int b = blockIdx.y;      // 16
    int tid = threadIdx.x;   // 128
    const float* wp = g_w + (size_t)b * S + chunk * 128;
    const float4* ep = (const float4*)(enc + ((size_t)b * S + chunk * 128) * D) + tid;
    float4 a0 = make_float4(0.f, 0.f, 0.f, 0.f);
    float4 a1 = make_float4(0.f, 0.f, 0.f, 0.f);
#pragma unroll 4
    for (int s = 0; s < 128; s += 2) {
        float w0 = wp[s], w1 = wp[s + 1];
        float4 e0 = ep[(size_t)s * (D / 4)];
        float4 e1 = ep[(size_t)(s + 1) * (D / 4)];
        a0.x += w0 * e0.x; a0.y += w0 * e0.y; a0.z += w0 * e0.z; a0.w += w0 * e0.w;
        a1.x += w1 * e1.x; a1.y += w1 * e1.y; a1.z += w1 * e1.z; a1.w += w1 * e1.w;
    }
    a0.x += a1.x; a0.y += a1.y; a0.z += a1.z; a0.w += a1.w;
    *(float4*)&g_part[((size_t)b * 64 + chunk) * D + tid * 4] = a0;
}

__global__ void ctx_reduce_kernel(float* __restrict__ out) {
    int b = blockIdx.x;
    int d = threadIdx.x;
    float acc = 0.f;
#pragma unroll
    for (int c = 0; c < 64; c++) acc += g_part[((size_t)b * 64 + c) * D + d];
    out[b * D + d] = acc;
}

// ---------------------------------------------------------------------------
extern "C" void kernel_launch(void* const* d_in, const int* in_sizes, int n_in,
                              void* d_out, int out_size) {
    const float* enc = (const float*)d_in[0];
    const float* hidden = (const float*)d_in[1];
    const float* W = (const float*)d_in[2];
    const float* bias = (const float*)d_in[3];
    const float* v = (const float*)d_in[4];
    float* out = (float*)d_out;

    cudaFuncSetAttribute(scores_kernel, cudaFuncAttributeMaxDynamicSharedMemorySize,
                         SMEM_BYTES);

    w1cvt_kernel<<<H, 256>>>(W);
    hb_kernel<<<B, 256>>>(hidden, W, bias);
    dim3 grid(8, (B * S) / MT);
    scores_kernel<<<grid, NTH, SMEM_BYTES>>>(enc, v);
    softmax_kernel<<<B, 1024>>>();
    dim3 g4(64, B);
    ctx_part_kernel<<<g4, 128>>>(enc);
    ctx_reduce_kernel<<<B, D>>>(out);
}